// round 6
// baseline (speedup 1.0000x reference)
#include <cuda_runtime.h>

#define TPB   256
#define GRID1 1216          // 152 SMs * 8
#define VSEG  500000        // voxels (row1 = i % VSEG)
#define VQ    (VSEG / 4)    // 125000 float4 voxel-groups
#define CSH   16.0f         // fixed softmax shift (z in [-10, 24] -> safe)
#define LN2   0.69314718055994531f
#define GAP_T 1.0e-3f       // recompute threshold on approx-z gap

// ---------------- scratch (device globals) ----------------
__device__ unsigned int g_count;
__device__ float        g_partials[GRID1];
__device__ float        g_rS;                // 1 / sum(exp(z - CSH))

// JAX threefry2x32 (partitionable): counter=(0,i), key=(0,42), out = x0^x1.
static __device__ __forceinline__ unsigned int tf_bits(unsigned int ctr) {
    const unsigned int ks0 = 0u;
    const unsigned int ks1 = 42u;
    const unsigned int ks2 = 0x1BD11BDAu ^ 42u;
    unsigned int x0 = ks0;
    unsigned int x1 = ctr + ks1;
#define TF_R(r) { x0 += x1; x1 = __funnelshift_l(x1, x1, (r)); x1 ^= x0; }
    TF_R(13) TF_R(15) TF_R(26) TF_R(6)   x0 += ks1; x1 += ks2 + 1u;
    TF_R(17) TF_R(29) TF_R(16) TF_R(24)  x0 += ks2; x1 += ks0 + 2u;
    TF_R(13) TF_R(15) TF_R(26) TF_R(6)   x0 += ks0; x1 += ks1 + 3u;
    TF_R(17) TF_R(29) TF_R(16) TF_R(24)  x0 += ks1; x1 += ks2 + 4u;
    TF_R(13) TF_R(15) TF_R(26) TF_R(6)   x0 += ks2; x1 += ks0 + 5u;
#undef TF_R
    return x0 ^ x1;
}

// FAST gumbel: |error| <= ~4e-5 absolute in z everywhere.
// u = f-1 (exact), w = 2-f = 1-u (exact, Sterbenz).
// inner t = -ln(u): MUFU.LG2 path for w >= 2^-7 (t >= 0.0078 -> rel err
// <= 3.2e-5); log1p series for w < 2^-7 (rel err <= 1.2e-7) -- this covers
// u->1 where winners live and MUFU's absolute error would blow up.
// Returns m2 = log2(t); caller does z = fma(-ln2, m2, e).
static __device__ __forceinline__ float gumbel_fast_l2(unsigned int i) {
    unsigned int b = tf_bits(i);
    float f = __uint_as_float((b >> 9) | 0x3f800000u);
    float u = f - 1.0f;
    float w = 2.0f - f;
    float t_ser = w * fmaf(w, fmaf(w, 0.33333333f, 0.5f), 1.0f);
    float t_muf = -LN2 * __log2f(u);          // u==0 -> +inf -> z=-inf, safe
    float t = (w < 0.0078125f) ? t_ser : t_muf;
    return __log2f(t);
}

// EXACT gumbel (bit-matches reference: libdevice logf) -- slow path only.
static __device__ __forceinline__ float gumbel_exact(unsigned int i) {
    unsigned int b = tf_bits(i);
    float f = __uint_as_float((b >> 9) | 0x3f800000u) - 1.0f;
    float u = fmaxf(f, 1.17549435e-38f);
    return -logf(-logf(u));
}

// ---------------- K1: z = e + g (fast), zero y_hard, shifted sum -----------
__global__ void __launch_bounds__(TPB)
k_main(const float4* __restrict__ e4, float4* __restrict__ z4,
       float4* __restrict__ yh4, int n8) {
    const int stride = gridDim.x * blockDim.x;
    float lsum = 0.f;
    const float4 zero4 = make_float4(0.f, 0.f, 0.f, 0.f);
    for (int i = blockIdx.x * blockDim.x + threadIdx.x; i < n8; i += stride) {
        const float4 ea = e4[2 * i];
        const float4 eb = e4[2 * i + 1];
        const unsigned int b = 8u * (unsigned int)i;
        float z0 = fmaf(-LN2, gumbel_fast_l2(b),      ea.x);
        float z1 = fmaf(-LN2, gumbel_fast_l2(b + 1u), ea.y);
        float z2 = fmaf(-LN2, gumbel_fast_l2(b + 2u), ea.z);
        float z3 = fmaf(-LN2, gumbel_fast_l2(b + 3u), ea.w);
        float z4v = fmaf(-LN2, gumbel_fast_l2(b + 4u), eb.x);
        float z5 = fmaf(-LN2, gumbel_fast_l2(b + 5u), eb.y);
        float z6 = fmaf(-LN2, gumbel_fast_l2(b + 6u), eb.z);
        float z7 = fmaf(-LN2, gumbel_fast_l2(b + 7u), eb.w);
        z4[2 * i]     = make_float4(z0, z1, z2, z3);
        z4[2 * i + 1] = make_float4(z4v, z5, z6, z7);
        yh4[2 * i]     = zero4;
        yh4[2 * i + 1] = zero4;
        float s01 = __expf(z0 - CSH) + __expf(z1 - CSH);
        float s23 = __expf(z2 - CSH) + __expf(z3 - CSH);
        float s45 = __expf(z4v - CSH) + __expf(z5 - CSH);
        float s67 = __expf(z6 - CSH) + __expf(z7 - CSH);
        lsum += (s01 + s23) + (s45 + s67);
    }
    #pragma unroll
    for (int o = 16; o; o >>= 1)
        lsum += __shfl_xor_sync(0xffffffffu, lsum, o);
    __shared__ float ssum[TPB / 32];
    __shared__ int   s_last;
    if ((threadIdx.x & 31) == 0) ssum[threadIdx.x >> 5] = lsum;
    __syncthreads();
    if (threadIdx.x < 32) {
        float vs = (threadIdx.x < (TPB / 32)) ? ssum[threadIdx.x] : 0.f;
        #pragma unroll
        for (int o = 16; o; o >>= 1)
            vs += __shfl_xor_sync(0xffffffffu, vs, o);
        if (threadIdx.x == 0) {
            g_partials[blockIdx.x] = vs;
            __threadfence();
            unsigned int t = atomicAdd(&g_count, 1u);
            s_last = (t == gridDim.x - 1u);
        }
    }
    __syncthreads();
    if (s_last) {
        float acc = 0.f;
        for (int i = threadIdx.x; i < (int)gridDim.x; i += TPB)
            acc += __ldcg(&g_partials[i]);
        #pragma unroll
        for (int o = 16; o; o >>= 1)
            acc += __shfl_xor_sync(0xffffffffu, acc, o);
        if ((threadIdx.x & 31) == 0) ssum[threadIdx.x >> 5] = acc;
        __syncthreads();
        if (threadIdx.x == 0) {
            float tot = 0.f;
            #pragma unroll
            for (int w = 0; w < TPB / 32; w++) tot += ssum[w];
            g_rS = 1.0f / tot;
            g_count = 0u;            // restore for next graph replay
        }
    }
}

// ---------------- K2: softmax finalize + top-2 argmax + exact fallback -----
// (64,8) block: thread (x,cy) owns voxels 4q..4q+3 over reps j=cy*4..cy*4+3.
// Tracks per-component (top1 z, idx, top2 z); combines chunks in ascending
// order (strict > keeps min-edge-id winner). If top1-top2 < GAP_T the voxel
// is recomputed bit-exactly (threefry + libdevice logf, reading e[]), so
// winners always match the exact-z semantics.
__global__ void __launch_bounds__(512)
k_out(float4* __restrict__ yz4, float* __restrict__ yh,
      const float* __restrict__ e) {
    const int x  = threadIdx.x;        // 0..63
    const int cy = threadIdx.y;        // 0..7
    const int q  = blockIdx.x * 64 + x;
    const bool act = (q < VQ);
    const float rS = g_rS;
    const float NINF = __int_as_float(0xff800000);

    float v1[4] = {NINF, NINF, NINF, NINF};
    float v2[4] = {NINF, NINF, NINF, NINF};
    int   i1[4] = {0, 0, 0, 0};

    if (act) {
        float4 zv[4];
        #pragma unroll
        for (int jj = 0; jj < 4; jj++)
            zv[jj] = yz4[q + (cy * 4 + jj) * VQ];
        #pragma unroll
        for (int jj = 0; jj < 4; jj++) {
            const int j = cy * 4 + jj;
            float4 yv;
            yv.x = __expf(zv[jj].x - CSH) * rS;
            yv.y = __expf(zv[jj].y - CSH) * rS;
            yv.z = __expf(zv[jj].z - CSH) * rS;
            yv.w = __expf(zv[jj].w - CSH) * rS;
            yz4[q + j * VQ] = yv;
            const int base = 4 * q + j * VSEG;
            const float zz[4] = {zv[jj].x, zv[jj].y, zv[jj].z, zv[jj].w};
            #pragma unroll
            for (int k = 0; k < 4; k++) {
                if (zz[k] > v1[k]) { v2[k] = v1[k]; v1[k] = zz[k]; i1[k] = base + k; }
                else               { v2[k] = fmaxf(v2[k], zz[k]); }
            }
        }
    }

    __shared__ float s1[8][64][4];
    __shared__ float s2[8][64][4];
    __shared__ int   si[8][64][4];
    #pragma unroll
    for (int k = 0; k < 4; k++) {
        s1[cy][x][k] = v1[k];
        s2[cy][x][k] = v2[k];
        si[cy][x][k] = i1[k];
    }
    __syncthreads();

    if (cy == 0 && act) {
        #pragma unroll
        for (int c = 1; c < 8; c++) {
            #pragma unroll
            for (int k = 0; k < 4; k++) {
                float b1 = s1[c][x][k];
                float b2 = s2[c][x][k];
                int   bi = si[c][x][k];
                if (b1 > v1[k]) {
                    v2[k] = fmaxf(v1[k], b2);
                    v1[k] = b1; i1[k] = bi;
                } else {
                    v2[k] = fmaxf(v2[k], b1);
                }
            }
        }
        #pragma unroll
        for (int k = 0; k < 4; k++) {
            if (v1[k] - v2[k] < GAP_T) {
                // ambiguous: recompute this voxel bit-exactly
                const int vox = 4 * q + k;
                float bz = NINF; int bi = vox;
                for (int j = 0; j < 32; j++) {
                    const int idx = vox + j * VSEG;
                    float zz = e[idx] + gumbel_exact((unsigned int)idx);
                    if (zz > bz) { bz = zz; bi = idx; }
                }
                v1[k] = bz; i1[k] = bi;
            }
            float yv = __expf(v1[k] - CSH) * rS;
            // straight-through arithmetic: (1 - y) + y, matching reference
            yh[i1[k]] = (1.0f - yv) + yv;
        }
    }
}

// ---------------- launch ----------------
extern "C" void kernel_launch(void* const* d_in, const int* in_sizes, int n_in,
                              void* d_out, int out_size) {
    const float* e = (const float*)d_in[0];
    const int E = in_sizes[0];
    float* y  = (float*)d_out;    // [0:E)  -> y
    float* yh = y + E;            // [E:2E) -> y_hard

    k_main<<<GRID1, TPB>>>((const float4*)e, (float4*)y, (float4*)yh, E / 8);
    dim3 blk(64, 8);
    int nblocks = (VQ + 63) / 64;   // 1954
    k_out<<<nblocks, blk>>>((float4*)y, yh, e);
}

// round 7
// speedup vs baseline: 1.2778x; 1.2778x over previous
#include <cuda_runtime.h>

#define TPB   256
#define GRID1 1216          // 152 SMs * 8
#define VSEG  500000        // voxels (row1 = i % VSEG)
#define VQ    (VSEG / 4)    // 125000 float4 voxel-groups
#define CSH   16.0f         // fixed softmax shift (z in [-10, 24] -> safe)
#define LN2   0.69314718055994531f
#define AMB_CAP 32768
#define GAP_REL 0.999f      // ambiguous if s2 >= s1 * GAP_REL (1e-3 rel gap)

// ---------------- scratch (device globals) ----------------
__device__ unsigned int g_count;
__device__ float        g_partials[GRID1];
__device__ float        g_rS;                // 1 / sum(exp(z - CSH))
__device__ unsigned int g_namb;              // ambiguous-voxel count
__device__ int          g_amb[AMB_CAP];      // ambiguous voxel ids

// JAX threefry2x32 (partitionable): counter=(0,i), key=(0,42), out = x0^x1.
static __device__ __forceinline__ unsigned int tf_bits(unsigned int ctr) {
    const unsigned int ks0 = 0u;
    const unsigned int ks1 = 42u;
    const unsigned int ks2 = 0x1BD11BDAu ^ 42u;
    unsigned int x0 = ks0;
    unsigned int x1 = ctr + ks1;
#define TF_R(r) { x0 += x1; x1 = __funnelshift_l(x1, x1, (r)); x1 ^= x0; }
    TF_R(13) TF_R(15) TF_R(26) TF_R(6)   x0 += ks1; x1 += ks2 + 1u;
    TF_R(17) TF_R(29) TF_R(16) TF_R(24)  x0 += ks2; x1 += ks0 + 2u;
    TF_R(13) TF_R(15) TF_R(26) TF_R(6)   x0 += ks0; x1 += ks1 + 3u;
    TF_R(17) TF_R(29) TF_R(16) TF_R(24)  x0 += ks1; x1 += ks2 + 4u;
    TF_R(13) TF_R(15) TF_R(26) TF_R(6)   x0 += ks2; x1 += ks0 + 5u;
#undef TF_R
    return x0 ^ x1;
}

// FAST gumbel (|dz| <= ~4e-5): u=f-1, w=2-f exact; inner -ln(u) via MUFU
// for w >= 2^-7, log1p series for w < 2^-7 (covers u->1 where winners live).
static __device__ __forceinline__ float gumbel_fast_l2(unsigned int i) {
    unsigned int b = tf_bits(i);
    float f = __uint_as_float((b >> 9) | 0x3f800000u);
    float u = f - 1.0f;
    float w = 2.0f - f;
    float t_ser = w * fmaf(w, fmaf(w, 0.33333333f, 0.5f), 1.0f);
    float t_muf = -LN2 * __log2f(u);
    float t = (w < 0.0078125f) ? t_ser : t_muf;
    return __log2f(t);
}

// EXACT gumbel (bit-matches reference: libdevice logf) -- fixup path only.
static __device__ __forceinline__ float gumbel_exact(unsigned int i) {
    unsigned int b = tf_bits(i);
    float f = __uint_as_float((b >> 9) | 0x3f800000u) - 1.0f;
    float u = fmaxf(f, 1.17549435e-38f);
    return -logf(-logf(u));
}

// ---------------- K1: s = exp(z-CSH), zero y_hard, reduce sum --------------
__global__ void __launch_bounds__(TPB)
k_main(const float4* __restrict__ e4, float4* __restrict__ s4,
       float4* __restrict__ yh4, int n8) {
    if (blockIdx.x == 0 && threadIdx.x == 0) g_namb = 0u;  // reset per replay
    const int stride = gridDim.x * blockDim.x;
    float lsum = 0.f;
    const float4 zero4 = make_float4(0.f, 0.f, 0.f, 0.f);
    for (int i = blockIdx.x * blockDim.x + threadIdx.x; i < n8; i += stride) {
        const float4 ea = e4[2 * i];
        const float4 eb = e4[2 * i + 1];
        const unsigned int b = 8u * (unsigned int)i;
        float z0 = fmaf(-LN2, gumbel_fast_l2(b),      ea.x);
        float z1 = fmaf(-LN2, gumbel_fast_l2(b + 1u), ea.y);
        float z2 = fmaf(-LN2, gumbel_fast_l2(b + 2u), ea.z);
        float z3 = fmaf(-LN2, gumbel_fast_l2(b + 3u), ea.w);
        float z4v = fmaf(-LN2, gumbel_fast_l2(b + 4u), eb.x);
        float z5 = fmaf(-LN2, gumbel_fast_l2(b + 5u), eb.y);
        float z6 = fmaf(-LN2, gumbel_fast_l2(b + 6u), eb.z);
        float z7 = fmaf(-LN2, gumbel_fast_l2(b + 7u), eb.w);
        float s0 = __expf(z0 - CSH), s1 = __expf(z1 - CSH);
        float s2 = __expf(z2 - CSH), s3 = __expf(z3 - CSH);
        float s5 = __expf(z4v - CSH), s6 = __expf(z5 - CSH);
        float s7 = __expf(z6 - CSH), s8 = __expf(z7 - CSH);
        s4[2 * i]     = make_float4(s0, s1, s2, s3);
        s4[2 * i + 1] = make_float4(s5, s6, s7, s8);
        yh4[2 * i]     = zero4;
        yh4[2 * i + 1] = zero4;
        lsum += ((s0 + s1) + (s2 + s3)) + ((s5 + s6) + (s7 + s8));
    }
    #pragma unroll
    for (int o = 16; o; o >>= 1)
        lsum += __shfl_xor_sync(0xffffffffu, lsum, o);
    __shared__ float ssum[TPB / 32];
    __shared__ int   s_last;
    if ((threadIdx.x & 31) == 0) ssum[threadIdx.x >> 5] = lsum;
    __syncthreads();
    if (threadIdx.x < 32) {
        float vs = (threadIdx.x < (TPB / 32)) ? ssum[threadIdx.x] : 0.f;
        #pragma unroll
        for (int o = 16; o; o >>= 1)
            vs += __shfl_xor_sync(0xffffffffu, vs, o);
        if (threadIdx.x == 0) {
            g_partials[blockIdx.x] = vs;
            __threadfence();
            unsigned int t = atomicAdd(&g_count, 1u);
            s_last = (t == gridDim.x - 1u);
        }
    }
    __syncthreads();
    if (s_last) {
        float acc = 0.f;
        for (int i = threadIdx.x; i < (int)gridDim.x; i += TPB)
            acc += __ldcg(&g_partials[i]);
        #pragma unroll
        for (int o = 16; o; o >>= 1)
            acc += __shfl_xor_sync(0xffffffffu, acc, o);
        if ((threadIdx.x & 31) == 0) ssum[threadIdx.x >> 5] = acc;
        __syncthreads();
        if (threadIdx.x == 0) {
            float tot = 0.f;
            #pragma unroll
            for (int w = 0; w < TPB / 32; w++) tot += ssum[w];
            g_rS = 1.0f / tot;
            g_count = 0u;            // restore for next graph replay
        }
    }
}

// ---------------- K2: y = s*rS + top-2 argmax; enqueue ambiguous -----------
// (64,8) block: thread (x,cy) owns voxels 4q..4q+3 over reps j=cy*4..cy*4+3.
// Argmax on s (monotonic in z). Strict > in ascending order keeps the
// min-edge-id winner. Ambiguous (rel gap < 1e-3) voxels go to g_amb for the
// exact fixup kernel; their yh stays 0 here.
__global__ void __launch_bounds__(512)
k_out(float4* __restrict__ ys4, float* __restrict__ yh) {
    const int x  = threadIdx.x;        // 0..63
    const int cy = threadIdx.y;        // 0..7
    const int q  = blockIdx.x * 64 + x;
    const bool act = (q < VQ);
    const float rS = g_rS;

    float v1[4] = {0.f, 0.f, 0.f, 0.f};   // s > 0 always
    float v2[4] = {0.f, 0.f, 0.f, 0.f};
    int   i1[4] = {0, 0, 0, 0};

    if (act) {
        float4 sv[4];
        #pragma unroll
        for (int jj = 0; jj < 4; jj++)
            sv[jj] = ys4[q + (cy * 4 + jj) * VQ];
        #pragma unroll
        for (int jj = 0; jj < 4; jj++) {
            const int j = cy * 4 + jj;
            float4 yv;
            yv.x = sv[jj].x * rS;
            yv.y = sv[jj].y * rS;
            yv.z = sv[jj].z * rS;
            yv.w = sv[jj].w * rS;
            ys4[q + j * VQ] = yv;
            const int base = 4 * q + j * VSEG;
            const float ss[4] = {sv[jj].x, sv[jj].y, sv[jj].z, sv[jj].w};
            #pragma unroll
            for (int k = 0; k < 4; k++) {
                if (ss[k] > v1[k]) { v2[k] = v1[k]; v1[k] = ss[k]; i1[k] = base + k; }
                else               { v2[k] = fmaxf(v2[k], ss[k]); }
            }
        }
    }

    __shared__ float s1m[8][64][4];
    __shared__ float s2m[8][64][4];
    __shared__ int   sim[8][64][4];
    #pragma unroll
    for (int k = 0; k < 4; k++) {
        s1m[cy][x][k] = v1[k];
        s2m[cy][x][k] = v2[k];
        sim[cy][x][k] = i1[k];
    }
    __syncthreads();

    if (cy == 0 && act) {
        #pragma unroll
        for (int c = 1; c < 8; c++) {
            #pragma unroll
            for (int k = 0; k < 4; k++) {
                float b1 = s1m[c][x][k];
                float b2 = s2m[c][x][k];
                int   bi = sim[c][x][k];
                if (b1 > v1[k]) {
                    v2[k] = fmaxf(v1[k], b2);
                    v1[k] = b1; i1[k] = bi;
                } else {
                    v2[k] = fmaxf(v2[k], b1);
                }
            }
        }
        #pragma unroll
        for (int k = 0; k < 4; k++) {
            if (v2[k] >= v1[k] * GAP_REL) {
                // ambiguous -> defer to exact fixup kernel
                unsigned int slot = atomicAdd(&g_namb, 1u);
                if (slot < AMB_CAP) {
                    g_amb[slot] = 4 * q + k;
                    continue;
                }
                // overflow (shouldn't happen): leave for fixup anyway impossible,
                // so just fall through and write the approx winner.
            }
            float yv = v1[k] * rS;
            // straight-through arithmetic: (1 - y) + y, matching reference
            yh[i1[k]] = (1.0f - yv) + yv;
        }
    }
}

// ---------------- K3: exact fixup, one warp per ambiguous voxel ------------
__global__ void __launch_bounds__(256)
k_fix(const float* __restrict__ e, const float* __restrict__ y,
      float* __restrict__ yh) {
    const unsigned int namb = min(g_namb, (unsigned int)AMB_CAP);
    const int warp = (blockIdx.x * blockDim.x + threadIdx.x) >> 5;
    const int lane = threadIdx.x & 31;
    const int nwarps = (gridDim.x * blockDim.x) >> 5;
    for (unsigned int a = warp; a < namb; a += nwarps) {
        const int vox = g_amb[a];
        const int idx = vox + lane * VSEG;
        float z = e[idx] + gumbel_exact((unsigned int)idx);
        int   bi = idx;
        // warp argmax, min-index tie-break (matches reference exactly)
        #pragma unroll
        for (int o = 16; o; o >>= 1) {
            float oz = __shfl_xor_sync(0xffffffffu, z, o);
            int   oi = __shfl_xor_sync(0xffffffffu, bi, o);
            if (oz > z || (oz == z && oi < bi)) { z = oz; bi = oi; }
        }
        if (lane == 0) {
            float yv = y[bi];
            yh[bi] = (1.0f - yv) + yv;
        }
    }
}

// ---------------- launch ----------------
extern "C" void kernel_launch(void* const* d_in, const int* in_sizes, int n_in,
                              void* d_out, int out_size) {
    const float* e = (const float*)d_in[0];
    const int E = in_sizes[0];
    float* y  = (float*)d_out;    // [0:E)  -> y
    float* yh = y + E;            // [E:2E) -> y_hard

    k_main<<<GRID1, TPB>>>((const float4*)e, (float4*)y, (float4*)yh, E / 8);
    dim3 blk(64, 8);
    int nblocks = (VQ + 63) / 64;   // 1954
    k_out<<<nblocks, blk>>>((float4*)y, yh);
    k_fix<<<128, 256>>>(e, y, yh);
}

// round 8
// speedup vs baseline: 1.3077x; 1.0234x over previous
#include <cuda_runtime.h>

#define TPB   256
#define GRID1 1216          // 152 SMs * 8 -> exactly fills the chip
#define VSEG  500000        // voxels (row1 = i % VSEG)
#define VQ    (VSEG / 4)    // 125000 float4 voxel-groups
#define CSH   16.0f         // fixed softmax shift (z in [-10, 24] -> safe)
#define LN2   0.69314718055994531f
#define AMB_CAP 32768
#define GAP_REL 0.999f      // ambiguous if s2 >= s1 * GAP_REL (1e-3 rel gap)

// threefry key schedule constants (key = (0, 42))
#define KS1   42u
#define KS2   0x1BD11BF0u   // 0x1BD11BDA ^ 42

// ---------------- scratch (device globals) ----------------
__device__ unsigned int g_count;
__device__ float        g_partials[GRID1];
__device__ float        g_rS;                // 1 / sum(exp(z - CSH))
__device__ unsigned int g_namb;              // ambiguous-voxel count
__device__ int          g_amb[AMB_CAP];      // ambiguous voxel ids

// ---- pipe-balanced add: force IMAD (fma pipe) via opaque multiplier ----
// d = a*one + d   (one==1 at runtime, unknown at compile time)
#define ADD_FMA(d, a) \
    asm("mad.lo.u32 %0, %1, %2, %0;" : "+r"(d) : "r"(a), "r"(one))
// d = one*imm + d
#define ADD_FMA_IMM(d, imm) \
    asm("mad.lo.u32 %0, %1, %2, %0;" : "+r"(d) : "r"(one), "n"(imm))

// JAX threefry2x32 (partitionable): counter=(0,i), key=(0,42), out = x0^x1.
// Adds forced onto the fma pipe (IMAD); SHF/LOP3 stay on alu -> ~balanced.
static __device__ __forceinline__ unsigned int tf_bits_bal(unsigned int ctr,
                                                           unsigned int one) {
    unsigned int x1 = KS1;
    ADD_FMA(x1, ctr);                      // x1 = ctr + 42 (IMAD)
    // round 1 specialized: x0 was ks0 = 0
    unsigned int x0 = x1;
    x1 = __funnelshift_l(x1, x1, 13) ^ x0;
#define TF_RF(r) { ADD_FMA(x0, x1); x1 = __funnelshift_l(x1, x1, (r)) ^ x0; }
    TF_RF(15) TF_RF(26) TF_RF(6)
    ADD_FMA_IMM(x0, KS1); ADD_FMA_IMM(x1, (KS2 + 1u));
    TF_RF(17) TF_RF(29) TF_RF(16) TF_RF(24)
    ADD_FMA_IMM(x0, KS2); ADD_FMA_IMM(x1, 2u);          // ks0 = 0 folded
    TF_RF(13) TF_RF(15) TF_RF(26) TF_RF(6)
    ADD_FMA_IMM(x1, (KS1 + 3u));                        // x0 += ks0 = 0 skip
    TF_RF(17) TF_RF(29) TF_RF(16) TF_RF(24)
    ADD_FMA_IMM(x0, KS1); ADD_FMA_IMM(x1, (KS2 + 4u));
    TF_RF(13) TF_RF(15) TF_RF(26) TF_RF(6)
    ADD_FMA_IMM(x0, KS2); ADD_FMA_IMM(x1, 5u);
#undef TF_RF
    return x0 ^ x1;
}

// FAST gumbel (|dz| <= ~4e-5): u=f-1, w=2-f exact; inner -ln(u) via MUFU
// for w >= 2^-7, log1p series for w < 2^-7 (covers u->1 where winners live).
static __device__ __forceinline__ float gumbel_fast_l2(unsigned int i,
                                                       unsigned int one) {
    unsigned int b = tf_bits_bal(i, one);
    float f = __uint_as_float((b >> 9) | 0x3f800000u);
    float u = f - 1.0f;
    float w = 2.0f - f;
    float t_ser = w * fmaf(w, fmaf(w, 0.33333333f, 0.5f), 1.0f);
    float t_muf = -LN2 * __log2f(u);
    float t = (w < 0.0078125f) ? t_ser : t_muf;
    return __log2f(t);
}

// EXACT gumbel (bit-matches reference: libdevice logf) -- fixup path only.
static __device__ __forceinline__ unsigned int tf_bits(unsigned int ctr) {
    unsigned int x0 = 0u;
    unsigned int x1 = ctr + KS1;
#define TF_R(r) { x0 += x1; x1 = __funnelshift_l(x1, x1, (r)); x1 ^= x0; }
    TF_R(13) TF_R(15) TF_R(26) TF_R(6)   x0 += KS1; x1 += KS2 + 1u;
    TF_R(17) TF_R(29) TF_R(16) TF_R(24)  x0 += KS2; x1 += 2u;
    TF_R(13) TF_R(15) TF_R(26) TF_R(6)   x1 += KS1 + 3u;
    TF_R(17) TF_R(29) TF_R(16) TF_R(24)  x0 += KS1; x1 += KS2 + 4u;
    TF_R(13) TF_R(15) TF_R(26) TF_R(6)   x0 += KS2; x1 += 5u;
#undef TF_R
    return x0 ^ x1;
}
static __device__ __forceinline__ float gumbel_exact(unsigned int i) {
    unsigned int b = tf_bits(i);
    float f = __uint_as_float((b >> 9) | 0x3f800000u) - 1.0f;
    float u = fmaxf(f, 1.17549435e-38f);
    return -logf(-logf(u));
}

// ---------------- K1: s = exp(z-CSH), zero y_hard, reduce sum --------------
__global__ void __launch_bounds__(TPB)
k_main(const float4* __restrict__ e4, float4* __restrict__ s4,
       float4* __restrict__ yh4, int n8, unsigned int one) {
    if (blockIdx.x == 0 && threadIdx.x == 0) g_namb = 0u;  // reset per replay
    const int stride = gridDim.x * blockDim.x;
    float lsumA = 0.f, lsumB = 0.f;
    const float4 zero4 = make_float4(0.f, 0.f, 0.f, 0.f);
    for (int i = blockIdx.x * blockDim.x + threadIdx.x; i < n8; i += stride) {
        const float4 ea = e4[2 * i];
        const float4 eb = e4[2 * i + 1];
        const unsigned int b = 8u * (unsigned int)i;
        float z0 = fmaf(-LN2, gumbel_fast_l2(b,      one), ea.x);
        float z1 = fmaf(-LN2, gumbel_fast_l2(b + 1u, one), ea.y);
        float z2 = fmaf(-LN2, gumbel_fast_l2(b + 2u, one), ea.z);
        float z3 = fmaf(-LN2, gumbel_fast_l2(b + 3u, one), ea.w);
        float z4v = fmaf(-LN2, gumbel_fast_l2(b + 4u, one), eb.x);
        float z5 = fmaf(-LN2, gumbel_fast_l2(b + 5u, one), eb.y);
        float z6 = fmaf(-LN2, gumbel_fast_l2(b + 6u, one), eb.z);
        float z7 = fmaf(-LN2, gumbel_fast_l2(b + 7u, one), eb.w);
        float s0 = __expf(z0 - CSH), s1 = __expf(z1 - CSH);
        float s2 = __expf(z2 - CSH), s3 = __expf(z3 - CSH);
        float s5 = __expf(z4v - CSH), s6 = __expf(z5 - CSH);
        float s7 = __expf(z6 - CSH), s8 = __expf(z7 - CSH);
        s4[2 * i]     = make_float4(s0, s1, s2, s3);
        s4[2 * i + 1] = make_float4(s5, s6, s7, s8);
        yh4[2 * i]     = zero4;
        yh4[2 * i + 1] = zero4;
        lsumA += ((s0 + s1) + (s2 + s3));
        lsumB += ((s5 + s6) + (s7 + s8));
    }
    float lsum = lsumA + lsumB;
    #pragma unroll
    for (int o = 16; o; o >>= 1)
        lsum += __shfl_xor_sync(0xffffffffu, lsum, o);
    __shared__ float ssum[TPB / 32];
    __shared__ int   s_last;
    if ((threadIdx.x & 31) == 0) ssum[threadIdx.x >> 5] = lsum;
    __syncthreads();
    if (threadIdx.x < 32) {
        float vs = (threadIdx.x < (TPB / 32)) ? ssum[threadIdx.x] : 0.f;
        #pragma unroll
        for (int o = 16; o; o >>= 1)
            vs += __shfl_xor_sync(0xffffffffu, vs, o);
        if (threadIdx.x == 0) {
            g_partials[blockIdx.x] = vs;
            __threadfence();
            unsigned int t = atomicAdd(&g_count, 1u);
            s_last = (t == gridDim.x - 1u);
        }
    }
    __syncthreads();
    if (s_last) {
        float acc = 0.f;
        for (int i = threadIdx.x; i < (int)gridDim.x; i += TPB)
            acc += __ldcg(&g_partials[i]);
        #pragma unroll
        for (int o = 16; o; o >>= 1)
            acc += __shfl_xor_sync(0xffffffffu, acc, o);
        if ((threadIdx.x & 31) == 0) ssum[threadIdx.x >> 5] = acc;
        __syncthreads();
        if (threadIdx.x == 0) {
            float tot = 0.f;
            #pragma unroll
            for (int w = 0; w < TPB / 32; w++) tot += ssum[w];
            g_rS = 1.0f / tot;
            g_count = 0u;            // restore for next graph replay
        }
    }
}

// ---------------- K2: y = s*rS + top-2 argmax; enqueue ambiguous -----------
__global__ void __launch_bounds__(512)
k_out(float4* __restrict__ ys4, float* __restrict__ yh) {
    const int x  = threadIdx.x;        // 0..63
    const int cy = threadIdx.y;        // 0..7
    const int q  = blockIdx.x * 64 + x;
    const bool act = (q < VQ);
    const float rS = g_rS;

    float v1[4] = {0.f, 0.f, 0.f, 0.f};   // s > 0 always
    float v2[4] = {0.f, 0.f, 0.f, 0.f};
    int   i1[4] = {0, 0, 0, 0};

    if (act) {
        float4 sv[4];
        #pragma unroll
        for (int jj = 0; jj < 4; jj++)
            sv[jj] = ys4[q + (cy * 4 + jj) * VQ];
        #pragma unroll
        for (int jj = 0; jj < 4; jj++) {
            const int j = cy * 4 + jj;
            float4 yv;
            yv.x = sv[jj].x * rS;
            yv.y = sv[jj].y * rS;
            yv.z = sv[jj].z * rS;
            yv.w = sv[jj].w * rS;
            ys4[q + j * VQ] = yv;
            const int base = 4 * q + j * VSEG;
            const float ss[4] = {sv[jj].x, sv[jj].y, sv[jj].z, sv[jj].w};
            #pragma unroll
            for (int k = 0; k < 4; k++) {
                if (ss[k] > v1[k]) { v2[k] = v1[k]; v1[k] = ss[k]; i1[k] = base + k; }
                else               { v2[k] = fmaxf(v2[k], ss[k]); }
            }
        }
    }

    __shared__ float s1m[8][64][4];
    __shared__ float s2m[8][64][4];
    __shared__ int   sim[8][64][4];
    #pragma unroll
    for (int k = 0; k < 4; k++) {
        s1m[cy][x][k] = v1[k];
        s2m[cy][x][k] = v2[k];
        sim[cy][x][k] = i1[k];
    }
    __syncthreads();

    if (cy == 0 && act) {
        #pragma unroll
        for (int c = 1; c < 8; c++) {
            #pragma unroll
            for (int k = 0; k < 4; k++) {
                float b1 = s1m[c][x][k];
                float b2 = s2m[c][x][k];
                int   bi = sim[c][x][k];
                if (b1 > v1[k]) {
                    v2[k] = fmaxf(v1[k], b2);
                    v1[k] = b1; i1[k] = bi;
                } else {
                    v2[k] = fmaxf(v2[k], b1);
                }
            }
        }
        #pragma unroll
        for (int k = 0; k < 4; k++) {
            if (v2[k] >= v1[k] * GAP_REL) {
                unsigned int slot = atomicAdd(&g_namb, 1u);
                if (slot < AMB_CAP) {
                    g_amb[slot] = 4 * q + k;
                    continue;
                }
            }
            float yv = v1[k] * rS;
            // straight-through arithmetic: (1 - y) + y, matching reference
            yh[i1[k]] = (1.0f - yv) + yv;
        }
    }
}

// ---------------- K3: exact fixup, one warp per ambiguous voxel ------------
__global__ void __launch_bounds__(256)
k_fix(const float* __restrict__ e, const float* __restrict__ y,
      float* __restrict__ yh) {
    const unsigned int namb = min(g_namb, (unsigned int)AMB_CAP);
    const int warp = (blockIdx.x * blockDim.x + threadIdx.x) >> 5;
    const int lane = threadIdx.x & 31;
    const int nwarps = (gridDim.x * blockDim.x) >> 5;
    for (unsigned int a = warp; a < namb; a += nwarps) {
        const int vox = g_amb[a];
        const int idx = vox + lane * VSEG;
        float z = e[idx] + gumbel_exact((unsigned int)idx);
        int   bi = idx;
        // warp argmax, min-index tie-break (matches reference exactly)
        #pragma unroll
        for (int o = 16; o; o >>= 1) {
            float oz = __shfl_xor_sync(0xffffffffu, z, o);
            int   oi = __shfl_xor_sync(0xffffffffu, bi, o);
            if (oz > z || (oz == z && oi < bi)) { z = oz; bi = oi; }
        }
        if (lane == 0) {
            float yv = y[bi];
            yh[bi] = (1.0f - yv) + yv;
        }
    }
}

// ---------------- launch ----------------
extern "C" void kernel_launch(void* const* d_in, const int* in_sizes, int n_in,
                              void* d_out, int out_size) {
    const float* e = (const float*)d_in[0];
    const int E = in_sizes[0];
    float* y  = (float*)d_out;    // [0:E)  -> y
    float* yh = y + E;            // [E:2E) -> y_hard

    k_main<<<GRID1, TPB>>>((const float4*)e, (float4*)y, (float4*)yh,
                           E / 8, 1u);
    dim3 blk(64, 8);
    int nblocks = (VQ + 63) / 64;   // 1954
    k_out<<<nblocks, blk>>>((float4*)y, yh);
    k_fix<<<128, 256>>>(e, y, yh);
}